// round 15
// baseline (speedup 1.0000x reference)
#include <cuda_runtime.h>
#include <cuda_fp16.h>
#include <math.h>
#include <stdint.h>

#define B_  2
#define T_  2048
#define M_  2048
#define H_  16
#define D_  128
#define BT_ (B_ * T_)
#define K_  M_

// ---------------------------------------------------------------------------
// Scratch (device globals: allocation-free per harness rules)
// ---------------------------------------------------------------------------
__device__ __half g_xh[(size_t)BT_ * M_];
__device__ __half g_qh[(size_t)BT_ * M_];
__device__ __half g_kh[(size_t)BT_ * M_];
__device__ __half g_vh[(size_t)BT_ * M_];
__device__ __half g_oh[(size_t)BT_ * M_];

// weights kept in NATURAL layout, just converted to fp16:
// wq/wk/wv: [H][M(k)][D(n)], wo: [K][N]
__device__ __half g_wq[(size_t)H_ * M_ * D_];
__device__ __half g_wk[(size_t)H_ * M_ * D_];
__device__ __half g_wv[(size_t)H_ * M_ * D_];
__device__ __half g_wo[(size_t)M_ * M_];

// ---------------------------------------------------------------------------
// PTX helpers (sm_80-class only: legal under plain sm_103 target)
// ---------------------------------------------------------------------------
__device__ __forceinline__ uint32_t s2u(const void* p) {
    uint32_t a;
    asm("{ .reg .u64 t; cvta.to.shared.u64 t, %1; cvt.u32.u64 %0, t; }"
        : "=r"(a) : "l"(p));
    return a;
}

__device__ __forceinline__ void cp16(uint32_t dst, const void* src) {
    asm volatile("cp.async.cg.shared.global [%0], [%1], 16;"
                 :: "r"(dst), "l"(src) : "memory");
}

#define LDSM4(r, a) \
    asm volatile("ldmatrix.sync.aligned.m8n8.x4.shared.b16 {%0,%1,%2,%3}, [%4];" \
                 : "=r"((r)[0]), "=r"((r)[1]), "=r"((r)[2]), "=r"((r)[3])        \
                 : "r"(a))

#define LDSM4T(r, a) \
    asm volatile("ldmatrix.sync.aligned.m8n8.x4.trans.shared.b16 {%0,%1,%2,%3}, [%4];" \
                 : "=r"((r)[0]), "=r"((r)[1]), "=r"((r)[2]), "=r"((r)[3])              \
                 : "r"(a))

__device__ __forceinline__ void mma16816(float* d, const uint32_t* a,
                                         uint32_t b0, uint32_t b1) {
    asm volatile(
        "mma.sync.aligned.m16n8k16.row.col.f32.f16.f16.f32 "
        "{%0,%1,%2,%3}, {%4,%5,%6,%7}, {%8,%9}, {%0,%1,%2,%3};"
        : "+f"(d[0]), "+f"(d[1]), "+f"(d[2]), "+f"(d[3])
        : "r"(a[0]), "r"(a[1]), "r"(a[2]), "r"(a[3]), "r"(b0), "r"(b1));
}

__device__ __forceinline__ uint32_t packh(float x, float y) {
    __half2 t = __halves2half2(__float2half_rn(x), __float2half_rn(y));
    return *(uint32_t*)&t;
}

// pack two fp32 -> f16x2 (lo, hi)
__device__ __forceinline__ uint32_t cvt2h(float lo, float hi) {
    uint32_t r;
    asm("cvt.rn.f16x2.f32 %0, %1, %2;" : "=r"(r) : "f"(hi), "f"(lo));
    return r;
}

// elementwise 2^x on packed halves
__device__ __forceinline__ uint32_t ex2h2(uint32_t x) {
    uint32_t r;
    asm("ex2.approx.f16x2 %0, %1;" : "=r"(r) : "r"(x));
    return r;
}

// ---------------------------------------------------------------------------
// One-launch convert of all fp32 inputs -> fp16 (no transposes needed).
// Slots (1,048,576 float4 each): 0,1 = x halves; 2..5 = wq, wk, wv, wo.
// ---------------------------------------------------------------------------
#define SLOT4 1048576

__global__ __launch_bounds__(256) void conv_all(
    const float* __restrict__ x,
    const float* __restrict__ waq, const float* __restrict__ wak,
    const float* __restrict__ wav, const float* __restrict__ wao,
    __half* __restrict__ xh,
    __half* __restrict__ wq, __half* __restrict__ wk,
    __half* __restrict__ wv, __half* __restrict__ wo)
{
    const int slot = blockIdx.y;
    const float* src;
    __half* dst;
    if (slot < 2)      { src = x + (size_t)slot * SLOT4 * 4;
                         dst = xh + (size_t)slot * SLOT4 * 4; }
    else if (slot == 2) { src = waq; dst = wq; }
    else if (slot == 3) { src = wak; dst = wk; }
    else if (slot == 4) { src = wav; dst = wv; }
    else                { src = wao; dst = wo; }

    int i = blockIdx.x * blockDim.x + threadIdx.x;
    float4 v = ((const float4*)src)[i];
    uint32_t* Hd = (uint32_t*)dst;
    Hd[2*i]   = packh(v.x, v.y);
    Hd[2*i+1] = packh(v.z, v.w);
}

// ---------------------------------------------------------------------------
// HMMA GEMM: 128x128 CTA tile, 4 warps (128 threads), warp tile 64x64.
// BK=64 (half the stage boundaries of BK=32), 3-stage cp.async.
// A: [m][k] smem (144B-padded rows) + LDSM4. B: natural [k][n] smem
// (272B-padded rows) + LDSM4T with immediate-consume MMA ordering.
// ---------------------------------------------------------------------------
#define ROWB      144                       // A row: 64 halves (128B) + 16B pad
#define BROWB     272                       // B row: 128 halves (256B) + 16B pad
#define AMAT_B    (128 * ROWB)              // 18432
#define BMAT_B    (64 * BROWB)              // 17408
#define STG_BYTES (AMAT_B + BMAT_B)         // 35840
#define NSTG      3
#define GEMM_SMEM (NSTG * STG_BYTES)        // 107520
#define KSTEPS    (K_ / 64)                 // 32
#define GTHREADS  128

__device__ __forceinline__ void load_stage(
    uint32_t buf, const __half* __restrict__ A,
    const __half* __restrict__ B, int ldb, int k0, int tid)
{
#pragma unroll
    for (int it = 0; it < 8; it++) {
        int idx = tid + it * GTHREADS;   // 0..1023
        // A chunk: 128 rows x 8 x 16B
        int ar = idx >> 3, ac = idx & 7;
        cp16(buf + (uint32_t)(ar * ROWB + ac * 16),
             A + (size_t)ar * K_ + k0 + ac * 8);
        // B chunk: 64 k-rows x 16 x 16B (natural [k][n] layout)
        int br = idx >> 4, bc = idx & 15;
        cp16(buf + AMAT_B + (uint32_t)(br * BROWB + bc * 16),
             B + (size_t)(k0 + br) * ldb + bc * 8);
    }
}

// Mainloop producing fp32 acc[4][8][4] (warp tile 64x64)
__device__ __forceinline__ void gemm_mainloop(
    uint32_t sb, const __half* A, const __half* B, int ldb, int tid,
    float acc[4][8][4])
{
    const int wid = tid >> 5, lane = tid & 31;
    const int warp_m = wid >> 1, warp_n = wid & 1;

    load_stage(sb,             A, B, ldb, 0,  tid);
    asm volatile("cp.async.commit_group;" ::: "memory");
    load_stage(sb + STG_BYTES, A, B, ldb, 64, tid);
    asm volatile("cp.async.commit_group;" ::: "memory");

#pragma unroll
    for (int i = 0; i < 4; i++)
#pragma unroll
        for (int j = 0; j < 8; j++)
#pragma unroll
            for (int r = 0; r < 4; r++) acc[i][j][r] = 0.f;

    const int lrow = lane & 15;
    const int lchk = (lane >> 4) * 16;

    for (int s = 0; s < KSTEPS; s++) {
        if (s + 1 < KSTEPS)
            asm volatile("cp.async.wait_group 1;" ::: "memory");
        else
            asm volatile("cp.async.wait_group 0;" ::: "memory");
        __syncthreads();

        if (s + 2 < KSTEPS) {
            load_stage(sb + (uint32_t)((s + 2) % NSTG) * STG_BYTES,
                       A, B, ldb, (s + 2) * 64, tid);
            asm volatile("cp.async.commit_group;" ::: "memory");
        }

        const uint32_t base = sb + (uint32_t)(s % NSTG) * STG_BYTES;
        const uint32_t bbase = base + AMAT_B;

#pragma unroll
        for (int kh = 0; kh < 4; kh++) {   // four k16 steps in BK=64
            uint32_t a4[4][4];
#pragma unroll
            for (int mi = 0; mi < 4; mi++) {
                uint32_t ad = base +
                    (uint32_t)((warp_m * 64 + mi * 16 + lrow) * ROWB)
                    + (uint32_t)(kh * 32 + lchk);
                LDSM4(a4[mi], ad);
            }
            // B via ldmatrix.trans on [k][n] rows, immediate consume
            const uint32_t brow = bbase +
                (uint32_t)((kh * 16 + lrow) * BROWB) + lchk
                + (uint32_t)(warp_n * 128);
#pragma unroll
            for (int nj = 0; nj < 4; nj++) {
                uint32_t bv[4];
                LDSM4T(bv, brow + nj * 32);
#pragma unroll
                for (int mi = 0; mi < 4; mi++) {
                    mma16816(acc[mi][2 * nj],     a4[mi], bv[0], bv[1]);
                    mma16816(acc[mi][2 * nj + 1], a4[mi], bv[2], bv[3]);
                }
            }
        }
    }
}

// ---------------------------------------------------------------------------
// QKV projection GEMM with fused RoPE epilogue for q/k.
// z: 0 = q (rope + log2e/128 scale -> base-2 logits), 1 = k (rope), 2 = v.
// B weights in natural [H][M(k)][D(n)] layout; blockIdx.y = head.
// ---------------------------------------------------------------------------
#define TILE_STR 130   // halves per row in epilogue staging tile

__global__ __launch_bounds__(GTHREADS) void gemm_qkv(
    const __half* __restrict__ xh,
    const __half* __restrict__ wq, const __half* __restrict__ wk,
    const __half* __restrict__ wv,
    __half* __restrict__ qh, __half* __restrict__ kh, __half* __restrict__ vh)
{
    extern __shared__ char smraw[];
    const uint32_t sb = s2u(smraw);
    const int tid = threadIdx.x;
    const int wid = tid >> 5, lane = tid & 31;
    const int warp_m = wid >> 1, warp_n = wid & 1;
    const int z = blockIdx.z;

    const __half* W = (z == 0) ? wq : (z == 1) ? wk : wv;
    __half* C       = (z == 0) ? qh : (z == 1) ? kh : vh;

    const int row0 = blockIdx.x * 128;
    const int head = blockIdx.y;           // n-tile == head (D == 128)
    const int col0 = head * 128;
    const __half* A = xh + (size_t)row0 * K_;
    const __half* B = W + (size_t)head * (M_ * D_);

    float acc[4][8][4];
    gemm_mainloop(sb, A, B, D_, tid, acc);

    const int grp = lane >> 2, tig = lane & 3;

    if (z == 2) {
#pragma unroll
        for (int mi = 0; mi < 4; mi++) {
#pragma unroll
            for (int ni = 0; ni < 8; ni++) {
                int r = row0 + warp_m * 64 + mi * 16 + grp;
                int c = col0 + warp_n * 64 + ni * 8 + tig * 2;
                *(uint32_t*)(C + (size_t)r * M_ + c) =
                    packh(acc[mi][ni][0], acc[mi][ni][1]);
                *(uint32_t*)(C + (size_t)(r + 8) * M_ + c) =
                    packh(acc[mi][ni][2], acc[mi][ni][3]);
            }
        }
        return;
    }

    // ---- fused RoPE epilogue (q/k) ----
    __half* tile = (__half*)smraw;   // 128 x TILE_STR halves = 33280 B
    __syncthreads();
#pragma unroll
    for (int mi = 0; mi < 4; mi++) {
#pragma unroll
        for (int ni = 0; ni < 8; ni++) {
            int rl = warp_m * 64 + mi * 16 + grp;
            int cl = warp_n * 64 + ni * 8 + tig * 2;
            *(uint32_t*)&tile[rl * TILE_STR + cl] =
                packh(acc[mi][ni][0], acc[mi][ni][1]);
            *(uint32_t*)&tile[(rl + 8) * TILE_STR + cl] =
                packh(acc[mi][ni][2], acc[mi][ni][3]);
        }
    }
    __syncthreads();

    // q: fold muP 1/128 AND log2(e) so attention logits are base-2
    const float scale = (z == 0) ? (1.44269504088896f / 128.0f) : 1.0f;
    const int d0 = lane * 2;
    const float freq0 = exp2f(-(float)d0 * 0.20762050593045952f);
    const float freq1 = exp2f(-(float)(d0 + 1) * 0.20762050593045952f);

#pragma unroll 4
    for (int rr = 0; rr < 32; rr++) {
        const int rl = wid * 32 + rr;
        const int t = (row0 + rl) & (T_ - 1);
        float s0, c0, s1, c1;
        sincosf((float)t * freq0, &s0, &c0);
        sincosf((float)t * freq1, &s1, &c1);

        __half2 ev = *(__half2*)&tile[rl * TILE_STR + d0];
        __half2 od = *(__half2*)&tile[rl * TILE_STR + d0 + 64];
        float e0 = __half2float(ev.x), e1 = __half2float(ev.y);
        float o0 = __half2float(od.x), o1 = __half2float(od.y);

        float r0e = (e0 * c0 - o0 * s0) * scale;
        float r1e = (e1 * c1 - o1 * s1) * scale;
        float r0o = (e0 * s0 + o0 * c0) * scale;
        float r1o = (e1 * s1 + o1 * c1) * scale;

        __half* Cp = C + (size_t)(row0 + rl) * M_ + col0;
        *(uint32_t*)(Cp + d0)      = packh(r0e, r1e);
        *(uint32_t*)(Cp + d0 + 64) = packh(r0o, r1o);
    }
}

// ---------------------------------------------------------------------------
// Output projection GEMM (fp32 out); wo in natural [K][N] layout
// ---------------------------------------------------------------------------
__global__ __launch_bounds__(GTHREADS) void gemm_out(
    const __half* __restrict__ A, const __half* __restrict__ wo,
    float* __restrict__ C)
{
    extern __shared__ char smraw[];
    const uint32_t sb = s2u(smraw);
    const int tid = threadIdx.x;
    const int wid = tid >> 5, lane = tid & 31;
    const int warp_m = wid >> 1, warp_n = wid & 1;

    const int row0 = blockIdx.x * 128;
    const int col0 = blockIdx.y * 128;
    const __half* Ap = A + (size_t)row0 * K_;
    const __half* Bp = wo + col0;

    float acc[4][8][4];
    gemm_mainloop(sb, Ap, Bp, M_, tid, acc);

    const int grp = lane >> 2, tig = lane & 3;
#pragma unroll
    for (int mi = 0; mi < 4; mi++) {
#pragma unroll
        for (int ni = 0; ni < 8; ni++) {
            int r = row0 + warp_m * 64 + mi * 16 + grp;
            int c = col0 + warp_n * 64 + ni * 8 + tig * 2;
            *(float2*)(C + (size_t)r * M_ + c) =
                make_float2(acc[mi][ni][0], acc[mi][ni][1]);
            *(float2*)(C + (size_t)(r + 8) * M_ + c) =
                make_float2(acc[mi][ni][2], acc[mi][ni][3]);
        }
    }
}

// ---------------------------------------------------------------------------
// HMMA causal flash attention: 128q x 64kv tiles, 8 warps, 2 CTAs/SM.
// Base-2 fixed-base softmax; ones-MMA row sums; packed ex2.approx.f16x2.
// ---------------------------------------------------------------------------
#define AROWB 272
#define AMAT  (64 * AROWB)            // 17408
#define QBYT  (128 * AROWB)           // 34816
#define KVK   QBYT
#define KVV   (QBYT + 2 * AMAT)
#define ATTN_SMEM (QBYT + 4 * AMAT)   // 104448
#define ONE2  0x3C003C00u             // half2 {1.0, 1.0}

__device__ __forceinline__ void load_half_tile(
    uint32_t dst, const __half* __restrict__ src, int b, int h, int j0, int tid)
{
#pragma unroll
    for (int it = 0; it < 4; it++) {
        int idx = tid + it * 256;
        int r = idx >> 4, c = idx & 15;
        cp16(dst + (uint32_t)(r * AROWB + c * 16),
             src + ((size_t)(b * T_ + j0 + r) * H_ + h) * D_ + c * 8);
    }
}

__global__ __launch_bounds__(256, 2) void attn_mma(
    const __half* __restrict__ qh, const __half* __restrict__ kh,
    const __half* __restrict__ vh, __half* __restrict__ oh)
{
    extern __shared__ char smraw[];
    const uint32_t sb = s2u(smraw);
    const int tid = threadIdx.x, wid = tid >> 5, lane = tid & 31;
    const int qi = (int)gridDim.x - 1 - (int)blockIdx.x;  // heavy tiles first
    const int h = blockIdx.y, b = blockIdx.z;
    const int i0 = qi * 128;
    const int numkv = (qi + 1) * 2;

    const __half* Qp = qh + ((size_t)(b * T_ + i0) * H_ + h) * D_;
#pragma unroll
    for (int it = 0; it < 8; it++) {
        int idx = tid + it * 256;
        int r = idx >> 4, c = idx & 15;
        cp16(sb + (uint32_t)(r * AROWB + c * 16),
             Qp + (size_t)r * (H_ * D_) + c * 8);
    }
    load_half_tile(sb + KVK, kh, b, h, 0, tid);
    load_half_tile(sb + KVV, vh, b, h, 0, tid);
    asm volatile("cp.async.commit_group;" ::: "memory");
    load_half_tile(sb + KVK + AMAT, kh, b, h, 64, tid);
    load_half_tile(sb + KVV + AMAT, vh, b, h, 64, tid);
    asm volatile("cp.async.commit_group;" ::: "memory");

    float oacc[16][4];
#pragma unroll
    for (int i = 0; i < 16; i++)
#pragma unroll
        for (int j = 0; j < 4; j++) oacc[i][j] = 0.f;
    float lacc[4] = {0.f, 0.f, 0.f, 0.f};   // ones-MMA row-sum accumulator

    const int lrow = lane & 15, lchk = (lane >> 4) * 16;
    const int grp = lane >> 2, tig = lane & 3;
    const int wrow = i0 + wid * 16;
    const int row0g = wrow + grp, row1g = row0g + 8;
    const uint32_t qln = sb + (uint32_t)((wid * 16 + lrow) * AROWB + lchk);

    for (int s = 0; s < numkv; s++) {
        if (s == 0)
            asm volatile("cp.async.wait_group 1;" ::: "memory");
        else
            asm volatile("cp.async.wait_group 2;" ::: "memory");
        __syncthreads();

        const uint32_t kbase = sb + KVK + (uint32_t)(s & 1) * AMAT;
        const uint32_t vbase = sb + KVV + (uint32_t)(s & 1) * AMAT;
        const int j0 = s * 64;

        // ---- S = Q * K^T (base-2 logits) ----
        float sacc[8][4];
#pragma unroll
        for (int i = 0; i < 8; i++)
#pragma unroll
            for (int j = 0; j < 4; j++) sacc[i][j] = 0.f;

        const uint32_t kln = kbase + (uint32_t)(lrow * AROWB + lchk);
#pragma unroll
        for (int kb = 0; kb < 8; kb++) {
            uint32_t a[4];
            LDSM4(a, qln + kb * 32);
#pragma unroll
            for (int ng = 0; ng < 4; ng++) {
                uint32_t bb[4];
                LDSM4(bb, kln + (uint32_t)(ng * (16 * AROWB)) + kb * 32);
                mma16816(sacc[2 * ng],     a, bb[0], bb[2]);
                mma16816(sacc[2 * ng + 1], a, bb[1], bb[3]);
            }
        }

        __syncthreads();
        if (s + 2 < numkv)
            load_half_tile(kbase, kh, b, h, (s + 2) * 64, tid);
        asm volatile("cp.async.commit_group;" ::: "memory");

        // ---- causal mask ----
        if (j0 + 63 > wrow) {
#pragma unroll
            for (int nb = 0; nb < 8; nb++) {
                int c0 = j0 + nb * 8 + tig * 2;
                if (c0     > row0g) sacc[nb][0] = -3.0e4f;
                if (c0 + 1 > row0g) sacc[nb][1] = -3.0e4f;
                if (c0     > row1g) sacc[nb][2] = -3.0e4f;
                if (c0 + 1 > row1g) sacc[nb][3] = -3.0e4f;
            }
        }

        // ---- P = 2^s (packed f16x2), ones-MMA row sums, fused PV ----
        const uint32_t vln = vbase + (uint32_t)(lrow * AROWB + lchk);
#pragma unroll
        for (int kk = 0; kk < 4; kk++) {
            uint32_t aP[4];
#pragma unroll
            for (int hf = 0; hf < 2; hf++) {
                int nb = 2 * kk + hf;
                aP[2 * hf]     = ex2h2(cvt2h(sacc[nb][0], sacc[nb][1]));
                aP[2 * hf + 1] = ex2h2(cvt2h(sacc[nb][2], sacc[nb][3]));
            }
            // exact row sums of rounded P (fp32 accumulate)
            mma16816(lacc, aP, ONE2, ONE2);

            const uint32_t vrow = vln + (uint32_t)(kk * (16 * AROWB));
#pragma unroll
            for (int ng = 0; ng < 8; ng++) {
                uint32_t bv[4];
                LDSM4T(bv, vrow + ng * 32);
                mma16816(oacc[2 * ng],     aP, bv[0], bv[1]);
                mma16816(oacc[2 * ng + 1], aP, bv[2], bv[3]);
            }
        }

        __syncthreads();
        if (s + 2 < numkv)
            load_half_tile(vbase, vh, b, h, (s + 2) * 64, tid);
        asm volatile("cp.async.commit_group;" ::: "memory");
    }

    // ---- epilogue: O / l -> fp16 ----
    const float inv0 = 1.0f / lacc[0], inv1 = 1.0f / lacc[2];
    const int orow0 = i0 + wid * 16 + grp;
    const size_t ob0 = ((size_t)(b * T_ + orow0) * H_ + h) * D_ + tig * 2;
    const size_t ob1 = ((size_t)(b * T_ + orow0 + 8) * H_ + h) * D_ + tig * 2;
#pragma unroll
    for (int ng = 0; ng < 16; ng++) {
        *(uint32_t*)(oh + ob0 + ng * 8) =
            packh(oacc[ng][0] * inv0, oacc[ng][1] * inv0);
        *(uint32_t*)(oh + ob1 + ng * 8) =
            packh(oacc[ng][2] * inv1, oacc[ng][3] * inv1);
    }
}

// ---------------------------------------------------------------------------
// Launch (single stream, 4 kernels)
// ---------------------------------------------------------------------------
extern "C" void kernel_launch(void* const* d_in, const int* in_sizes, int n_in,
                              void* d_out, int out_size)
{
    const float* x    = (const float*)d_in[0];
    const float* w_aq = (const float*)d_in[1];
    const float* w_ak = (const float*)d_in[2];
    const float* w_av = (const float*)d_in[3];
    const float* w_ao = (const float*)d_in[4];
    float* out = (float*)d_out;

    __half *xh, *qh, *kh, *vh, *oh;
    cudaGetSymbolAddress((void**)&xh, g_xh);
    cudaGetSymbolAddress((void**)&qh, g_qh);
    cudaGetSymbolAddress((void**)&kh, g_kh);
    cudaGetSymbolAddress((void**)&vh, g_vh);
    cudaGetSymbolAddress((void**)&oh, g_oh);

    __half *wq, *wk, *wv, *wo;
    cudaGetSymbolAddress((void**)&wq, g_wq);
    cudaGetSymbolAddress((void**)&wk, g_wk);
    cudaGetSymbolAddress((void**)&wv, g_wv);
    cudaGetSymbolAddress((void**)&wo, g_wo);

    // One-launch fp32 -> fp16 conversion of x + all weights (no transposes)
    dim3 cg(4096, 6);
    conv_all<<<cg, 256>>>(x, w_aq, w_ak, w_av, w_ao, xh, wq, wk, wv, wo);

    // QKV projections with fused RoPE epilogue (4-warp fat-tile GEMM, BK=64)
    cudaFuncSetAttribute(gemm_qkv,
                         cudaFuncAttributeMaxDynamicSharedMemorySize, GEMM_SMEM);
    cudaFuncSetAttribute(gemm_out,
                         cudaFuncAttributeMaxDynamicSharedMemorySize, GEMM_SMEM);
    dim3 gg(BT_ / 128, H_, 3);
    gemm_qkv<<<gg, GTHREADS, GEMM_SMEM>>>(xh, wq, wk, wv, qh, kh, vh);

    // HMMA flash attention -> oh (2 CTAs/SM)
    cudaFuncSetAttribute(attn_mma, cudaFuncAttributeMaxDynamicSharedMemorySize,
                         ATTN_SMEM);
    dim3 ga(T_ / 128, H_, B_);
    attn_mma<<<ga, 256, ATTN_SMEM>>>(qh, kh, vh, oh);

    // Output projection -> fp32 out
    dim3 ggo(BT_ / 128, M_ / 128, 1);
    gemm_out<<<ggo, GTHREADS, GEMM_SMEM>>>(oh, wo, out);
}

// round 16
// speedup vs baseline: 1.0784x; 1.0784x over previous
#include <cuda_runtime.h>
#include <cuda_fp16.h>
#include <math.h>
#include <stdint.h>

#define B_  2
#define T_  2048
#define M_  2048
#define H_  16
#define D_  128
#define BT_ (B_ * T_)
#define K_  M_

// ---------------------------------------------------------------------------
// Scratch (device globals: allocation-free per harness rules)
// ---------------------------------------------------------------------------
__device__ __half g_xh[(size_t)BT_ * M_];
__device__ __half g_qh[(size_t)BT_ * M_];
__device__ __half g_kh[(size_t)BT_ * M_];
__device__ __half g_vh[(size_t)BT_ * M_];
__device__ __half g_oh[(size_t)BT_ * M_];

// weights kept in NATURAL layout, just converted to fp16:
// wq/wk/wv: [H][M(k)][D(n)], wo: [K][N]
__device__ __half g_wq[(size_t)H_ * M_ * D_];
__device__ __half g_wk[(size_t)H_ * M_ * D_];
__device__ __half g_wv[(size_t)H_ * M_ * D_];
__device__ __half g_wo[(size_t)M_ * M_];

// ---------------------------------------------------------------------------
// PTX helpers (sm_80-class only: legal under plain sm_103 target)
// ---------------------------------------------------------------------------
__device__ __forceinline__ uint32_t s2u(const void* p) {
    uint32_t a;
    asm("{ .reg .u64 t; cvta.to.shared.u64 t, %1; cvt.u32.u64 %0, t; }"
        : "=r"(a) : "l"(p));
    return a;
}

__device__ __forceinline__ void cp16(uint32_t dst, const void* src) {
    asm volatile("cp.async.cg.shared.global [%0], [%1], 16;"
                 :: "r"(dst), "l"(src) : "memory");
}

#define LDSM4(r, a) \
    asm volatile("ldmatrix.sync.aligned.m8n8.x4.shared.b16 {%0,%1,%2,%3}, [%4];" \
                 : "=r"((r)[0]), "=r"((r)[1]), "=r"((r)[2]), "=r"((r)[3])        \
                 : "r"(a))

#define LDSM4T(r, a) \
    asm volatile("ldmatrix.sync.aligned.m8n8.x4.trans.shared.b16 {%0,%1,%2,%3}, [%4];" \
                 : "=r"((r)[0]), "=r"((r)[1]), "=r"((r)[2]), "=r"((r)[3])              \
                 : "r"(a))

__device__ __forceinline__ void mma16816(float* d, const uint32_t* a,
                                         uint32_t b0, uint32_t b1) {
    asm volatile(
        "mma.sync.aligned.m16n8k16.row.col.f32.f16.f16.f32 "
        "{%0,%1,%2,%3}, {%4,%5,%6,%7}, {%8,%9}, {%0,%1,%2,%3};"
        : "+f"(d[0]), "+f"(d[1]), "+f"(d[2]), "+f"(d[3])
        : "r"(a[0]), "r"(a[1]), "r"(a[2]), "r"(a[3]), "r"(b0), "r"(b1));
}

__device__ __forceinline__ uint32_t packh(float x, float y) {
    __half2 t = __halves2half2(__float2half_rn(x), __float2half_rn(y));
    return *(uint32_t*)&t;
}

// pack two fp32 -> f16x2 (lo, hi)
__device__ __forceinline__ uint32_t cvt2h(float lo, float hi) {
    uint32_t r;
    asm("cvt.rn.f16x2.f32 %0, %1, %2;" : "=r"(r) : "f"(hi), "f"(lo));
    return r;
}

// elementwise 2^x on packed halves
__device__ __forceinline__ uint32_t ex2h2(uint32_t x) {
    uint32_t r;
    asm("ex2.approx.f16x2 %0, %1;" : "=r"(r) : "r"(x));
    return r;
}

// ---------------------------------------------------------------------------
// One-launch convert of all fp32 inputs -> fp16 (no transposes needed).
// Slots (1,048,576 float4 each): 0,1 = x halves; 2..5 = wq, wk, wv, wo.
// ---------------------------------------------------------------------------
#define SLOT4 1048576

__global__ __launch_bounds__(256) void conv_all(
    const float* __restrict__ x,
    const float* __restrict__ waq, const float* __restrict__ wak,
    const float* __restrict__ wav, const float* __restrict__ wao,
    __half* __restrict__ xh,
    __half* __restrict__ wq, __half* __restrict__ wk,
    __half* __restrict__ wv, __half* __restrict__ wo)
{
    const int slot = blockIdx.y;
    const float* src;
    __half* dst;
    if (slot < 2)      { src = x + (size_t)slot * SLOT4 * 4;
                         dst = xh + (size_t)slot * SLOT4 * 4; }
    else if (slot == 2) { src = waq; dst = wq; }
    else if (slot == 3) { src = wak; dst = wk; }
    else if (slot == 4) { src = wav; dst = wv; }
    else                { src = wao; dst = wo; }

    int i = blockIdx.x * blockDim.x + threadIdx.x;
    float4 v = ((const float4*)src)[i];
    uint32_t* Hd = (uint32_t*)dst;
    Hd[2*i]   = packh(v.x, v.y);
    Hd[2*i+1] = packh(v.z, v.w);
}

// ---------------------------------------------------------------------------
// HMMA GEMM: 128x128 CTA tile, 4 warps (128 threads), warp tile 64x64.
// BK=32, 4-stage cp.async pipeline (wait_group 2 -> prefetch distance 3).
// A: [m][k] smem + LDSM4. B: natural [k][n] smem + LDSM4T, immediate consume.
// ---------------------------------------------------------------------------
#define ROWB      80
#define BROWB     272                       // B tile row: 128 halves + pad
#define AMAT_B    (128 * ROWB)              // 10240
#define BMAT_B    (32 * BROWB)              // 8704
#define STG_BYTES (AMAT_B + BMAT_B)         // 18944
#define NSTG      4
#define GEMM_SMEM (NSTG * STG_BYTES)        // 75776
#define KSTEPS    (K_ / 32)                 // 64
#define GTHREADS  128

__device__ __forceinline__ void load_stage(
    uint32_t buf, const __half* __restrict__ A,
    const __half* __restrict__ B, int ldb, int k0, int tid)
{
#pragma unroll
    for (int it = 0; it < 4; it++) {
        int idx = tid + it * GTHREADS;   // 0..511
        // A chunk: 128 rows x 4 x 16B
        int ar = idx >> 2, ac = idx & 3;
        cp16(buf + (uint32_t)(ar * ROWB + ac * 16),
             A + (size_t)ar * K_ + k0 + ac * 8);
        // B chunk: 32 k-rows x 16 x 16B (natural [k][n] layout)
        int br = idx >> 4, bc = idx & 15;
        cp16(buf + AMAT_B + (uint32_t)(br * BROWB + bc * 16),
             B + (size_t)(k0 + br) * ldb + bc * 8);
    }
}

// Mainloop producing fp32 acc[4][8][4] (warp tile 64x64)
__device__ __forceinline__ void gemm_mainloop(
    uint32_t sb, const __half* A, const __half* B, int ldb, int tid,
    float acc[4][8][4])
{
    const int wid = tid >> 5, lane = tid & 31;
    const int warp_m = wid >> 1, warp_n = wid & 1;

    load_stage(sb,                 A, B, ldb, 0,  tid);
    asm volatile("cp.async.commit_group;" ::: "memory");
    load_stage(sb + STG_BYTES,     A, B, ldb, 32, tid);
    asm volatile("cp.async.commit_group;" ::: "memory");
    load_stage(sb + 2 * STG_BYTES, A, B, ldb, 64, tid);
    asm volatile("cp.async.commit_group;" ::: "memory");

#pragma unroll
    for (int i = 0; i < 4; i++)
#pragma unroll
        for (int j = 0; j < 8; j++)
#pragma unroll
            for (int r = 0; r < 4; r++) acc[i][j][r] = 0.f;

    const int lrow = lane & 15;
    const int lchk = (lane >> 4) * 16;

    for (int s = 0; s < KSTEPS; s++) {
        if (s + 1 < KSTEPS)
            asm volatile("cp.async.wait_group 2;" ::: "memory");
        else
            asm volatile("cp.async.wait_group 0;" ::: "memory");
        __syncthreads();

        if (s + 3 < KSTEPS) {
            load_stage(sb + (uint32_t)((s + 3) % NSTG) * STG_BYTES,
                       A, B, ldb, (s + 3) * 32, tid);
            asm volatile("cp.async.commit_group;" ::: "memory");
        }

        const uint32_t base = sb + (uint32_t)(s % NSTG) * STG_BYTES;
        const uint32_t bbase = base + AMAT_B;

#pragma unroll
        for (int kh = 0; kh < 2; kh++) {
            uint32_t a4[4][4];
#pragma unroll
            for (int mi = 0; mi < 4; mi++) {
                uint32_t ad = base +
                    (uint32_t)((warp_m * 64 + mi * 16 + lrow) * ROWB)
                    + (uint32_t)(kh * 32 + lchk);
                LDSM4(a4[mi], ad);
            }
            // B via ldmatrix.trans on [k][n] rows (V-operand pattern)
            const uint32_t brow = bbase +
                (uint32_t)((kh * 16 + lrow) * BROWB) + lchk
                + (uint32_t)(warp_n * 128);
#pragma unroll
            for (int nj = 0; nj < 4; nj++) {
                uint32_t bv[4];
                LDSM4T(bv, brow + nj * 32);
#pragma unroll
                for (int mi = 0; mi < 4; mi++) {
                    mma16816(acc[mi][2 * nj],     a4[mi], bv[0], bv[1]);
                    mma16816(acc[mi][2 * nj + 1], a4[mi], bv[2], bv[3]);
                }
            }
        }
    }
}

// ---------------------------------------------------------------------------
// QKV projection GEMM with fused RoPE epilogue for q/k.
// z: 0 = q (rope + log2e/128 scale -> base-2 logits), 1 = k (rope), 2 = v.
// B weights in natural [H][M(k)][D(n)] layout; blockIdx.y = head.
// ---------------------------------------------------------------------------
#define TILE_STR 130   // halves per row in epilogue staging tile

__global__ __launch_bounds__(GTHREADS) void gemm_qkv(
    const __half* __restrict__ xh,
    const __half* __restrict__ wq, const __half* __restrict__ wk,
    const __half* __restrict__ wv,
    __half* __restrict__ qh, __half* __restrict__ kh, __half* __restrict__ vh)
{
    extern __shared__ char smraw[];
    const uint32_t sb = s2u(smraw);
    const int tid = threadIdx.x;
    const int wid = tid >> 5, lane = tid & 31;
    const int warp_m = wid >> 1, warp_n = wid & 1;
    const int z = blockIdx.z;

    const __half* W = (z == 0) ? wq : (z == 1) ? wk : wv;
    __half* C       = (z == 0) ? qh : (z == 1) ? kh : vh;

    const int row0 = blockIdx.x * 128;
    const int head = blockIdx.y;           // n-tile == head (D == 128)
    const int col0 = head * 128;
    const __half* A = xh + (size_t)row0 * K_;
    const __half* B = W + (size_t)head * (M_ * D_);

    float acc[4][8][4];
    gemm_mainloop(sb, A, B, D_, tid, acc);

    const int grp = lane >> 2, tig = lane & 3;

    if (z == 2) {
#pragma unroll
        for (int mi = 0; mi < 4; mi++) {
#pragma unroll
            for (int ni = 0; ni < 8; ni++) {
                int r = row0 + warp_m * 64 + mi * 16 + grp;
                int c = col0 + warp_n * 64 + ni * 8 + tig * 2;
                *(uint32_t*)(C + (size_t)r * M_ + c) =
                    packh(acc[mi][ni][0], acc[mi][ni][1]);
                *(uint32_t*)(C + (size_t)(r + 8) * M_ + c) =
                    packh(acc[mi][ni][2], acc[mi][ni][3]);
            }
        }
        return;
    }

    // ---- fused RoPE epilogue (q/k) ----
    __half* tile = (__half*)smraw;   // 128 x TILE_STR halves = 33280 B
    __syncthreads();
#pragma unroll
    for (int mi = 0; mi < 4; mi++) {
#pragma unroll
        for (int ni = 0; ni < 8; ni++) {
            int rl = warp_m * 64 + mi * 16 + grp;
            int cl = warp_n * 64 + ni * 8 + tig * 2;
            *(uint32_t*)&tile[rl * TILE_STR + cl] =
                packh(acc[mi][ni][0], acc[mi][ni][1]);
            *(uint32_t*)&tile[(rl + 8) * TILE_STR + cl] =
                packh(acc[mi][ni][2], acc[mi][ni][3]);
        }
    }
    __syncthreads();

    // q: fold muP 1/128 AND log2(e) so attention logits are base-2
    const float scale = (z == 0) ? (1.44269504088896f / 128.0f) : 1.0f;
    const int d0 = lane * 2;
    const float freq0 = exp2f(-(float)d0 * 0.20762050593045952f);
    const float freq1 = exp2f(-(float)(d0 + 1) * 0.20762050593045952f);

#pragma unroll 4
    for (int rr = 0; rr < 32; rr++) {
        const int rl = wid * 32 + rr;
        const int t = (row0 + rl) & (T_ - 1);
        float s0, c0, s1, c1;
        sincosf((float)t * freq0, &s0, &c0);
        sincosf((float)t * freq1, &s1, &c1);

        __half2 ev = *(__half2*)&tile[rl * TILE_STR + d0];
        __half2 od = *(__half2*)&tile[rl * TILE_STR + d0 + 64];
        float e0 = __half2float(ev.x), e1 = __half2float(ev.y);
        float o0 = __half2float(od.x), o1 = __half2float(od.y);

        float r0e = (e0 * c0 - o0 * s0) * scale;
        float r1e = (e1 * c1 - o1 * s1) * scale;
        float r0o = (e0 * s0 + o0 * c0) * scale;
        float r1o = (e1 * s1 + o1 * c1) * scale;

        __half* Cp = C + (size_t)(row0 + rl) * M_ + col0;
        *(uint32_t*)(Cp + d0)      = packh(r0e, r1e);
        *(uint32_t*)(Cp + d0 + 64) = packh(r0o, r1o);
    }
}

// ---------------------------------------------------------------------------
// Output projection GEMM (fp32 out); wo in natural [K][N] layout
// ---------------------------------------------------------------------------
__global__ __launch_bounds__(GTHREADS) void gemm_out(
    const __half* __restrict__ A, const __half* __restrict__ wo,
    float* __restrict__ C)
{
    extern __shared__ char smraw[];
    const uint32_t sb = s2u(smraw);
    const int tid = threadIdx.x;
    const int wid = tid >> 5, lane = tid & 31;
    const int warp_m = wid >> 1, warp_n = wid & 1;

    const int row0 = blockIdx.x * 128;
    const int col0 = blockIdx.y * 128;
    const __half* Ap = A + (size_t)row0 * K_;
    const __half* Bp = wo + col0;

    float acc[4][8][4];
    gemm_mainloop(sb, Ap, Bp, M_, tid, acc);

    const int grp = lane >> 2, tig = lane & 3;
#pragma unroll
    for (int mi = 0; mi < 4; mi++) {
#pragma unroll
        for (int ni = 0; ni < 8; ni++) {
            int r = row0 + warp_m * 64 + mi * 16 + grp;
            int c = col0 + warp_n * 64 + ni * 8 + tig * 2;
            *(float2*)(C + (size_t)r * M_ + c) =
                make_float2(acc[mi][ni][0], acc[mi][ni][1]);
            *(float2*)(C + (size_t)(r + 8) * M_ + c) =
                make_float2(acc[mi][ni][2], acc[mi][ni][3]);
        }
    }
}

// ---------------------------------------------------------------------------
// HMMA causal flash attention: 128q x 64kv tiles, 8 warps, 2 CTAs/SM.
// Base-2 fixed-base softmax; ones-MMA row sums; packed ex2.approx.f16x2.
// ---------------------------------------------------------------------------
#define AROWB 272
#define AMAT  (64 * AROWB)            // 17408
#define QBYT  (128 * AROWB)           // 34816
#define KVK   QBYT
#define KVV   (QBYT + 2 * AMAT)
#define ATTN_SMEM (QBYT + 4 * AMAT)   // 104448
#define ONE2  0x3C003C00u             // half2 {1.0, 1.0}

__device__ __forceinline__ void load_half_tile(
    uint32_t dst, const __half* __restrict__ src, int b, int h, int j0, int tid)
{
#pragma unroll
    for (int it = 0; it < 4; it++) {
        int idx = tid + it * 256;
        int r = idx >> 4, c = idx & 15;
        cp16(dst + (uint32_t)(r * AROWB + c * 16),
             src + ((size_t)(b * T_ + j0 + r) * H_ + h) * D_ + c * 8);
    }
}

__global__ __launch_bounds__(256, 2) void attn_mma(
    const __half* __restrict__ qh, const __half* __restrict__ kh,
    const __half* __restrict__ vh, __half* __restrict__ oh)
{
    extern __shared__ char smraw[];
    const uint32_t sb = s2u(smraw);
    const int tid = threadIdx.x, wid = tid >> 5, lane = tid & 31;
    const int qi = (int)gridDim.x - 1 - (int)blockIdx.x;  // heavy tiles first
    const int h = blockIdx.y, b = blockIdx.z;
    const int i0 = qi * 128;
    const int numkv = (qi + 1) * 2;

    const __half* Qp = qh + ((size_t)(b * T_ + i0) * H_ + h) * D_;
#pragma unroll
    for (int it = 0; it < 8; it++) {
        int idx = tid + it * 256;
        int r = idx >> 4, c = idx & 15;
        cp16(sb + (uint32_t)(r * AROWB + c * 16),
             Qp + (size_t)r * (H_ * D_) + c * 8);
    }
    load_half_tile(sb + KVK, kh, b, h, 0, tid);
    load_half_tile(sb + KVV, vh, b, h, 0, tid);
    asm volatile("cp.async.commit_group;" ::: "memory");
    load_half_tile(sb + KVK + AMAT, kh, b, h, 64, tid);
    load_half_tile(sb + KVV + AMAT, vh, b, h, 64, tid);
    asm volatile("cp.async.commit_group;" ::: "memory");

    float oacc[16][4];
#pragma unroll
    for (int i = 0; i < 16; i++)
#pragma unroll
        for (int j = 0; j < 4; j++) oacc[i][j] = 0.f;
    float lacc[4] = {0.f, 0.f, 0.f, 0.f};   // ones-MMA row-sum accumulator

    const int lrow = lane & 15, lchk = (lane >> 4) * 16;
    const int grp = lane >> 2, tig = lane & 3;
    const int wrow = i0 + wid * 16;
    const int row0g = wrow + grp, row1g = row0g + 8;
    const uint32_t qln = sb + (uint32_t)((wid * 16 + lrow) * AROWB + lchk);

    for (int s = 0; s < numkv; s++) {
        if (s == 0)
            asm volatile("cp.async.wait_group 1;" ::: "memory");
        else
            asm volatile("cp.async.wait_group 2;" ::: "memory");
        __syncthreads();

        const uint32_t kbase = sb + KVK + (uint32_t)(s & 1) * AMAT;
        const uint32_t vbase = sb + KVV + (uint32_t)(s & 1) * AMAT;
        const int j0 = s * 64;

        // ---- S = Q * K^T (base-2 logits) ----
        float sacc[8][4];
#pragma unroll
        for (int i = 0; i < 8; i++)
#pragma unroll
            for (int j = 0; j < 4; j++) sacc[i][j] = 0.f;

        const uint32_t kln = kbase + (uint32_t)(lrow * AROWB + lchk);
#pragma unroll
        for (int kb = 0; kb < 8; kb++) {
            uint32_t a[4];
            LDSM4(a, qln + kb * 32);
#pragma unroll
            for (int ng = 0; ng < 4; ng++) {
                uint32_t bb[4];
                LDSM4(bb, kln + (uint32_t)(ng * (16 * AROWB)) + kb * 32);
                mma16816(sacc[2 * ng],     a, bb[0], bb[2]);
                mma16816(sacc[2 * ng + 1], a, bb[1], bb[3]);
            }
        }

        __syncthreads();
        if (s + 2 < numkv)
            load_half_tile(kbase, kh, b, h, (s + 2) * 64, tid);
        asm volatile("cp.async.commit_group;" ::: "memory");

        // ---- causal mask ----
        if (j0 + 63 > wrow) {
#pragma unroll
            for (int nb = 0; nb < 8; nb++) {
                int c0 = j0 + nb * 8 + tig * 2;
                if (c0     > row0g) sacc[nb][0] = -3.0e4f;
                if (c0 + 1 > row0g) sacc[nb][1] = -3.0e4f;
                if (c0     > row1g) sacc[nb][2] = -3.0e4f;
                if (c0 + 1 > row1g) sacc[nb][3] = -3.0e4f;
            }
        }

        // ---- P = 2^s (packed f16x2), ones-MMA row sums, fused PV ----
        const uint32_t vln = vbase + (uint32_t)(lrow * AROWB + lchk);
#pragma unroll
        for (int kk = 0; kk < 4; kk++) {
            uint32_t aP[4];
#pragma unroll
            for (int hf = 0; hf < 2; hf++) {
                int nb = 2 * kk + hf;
                aP[2 * hf]     = ex2h2(cvt2h(sacc[nb][0], sacc[nb][1]));
                aP[2 * hf + 1] = ex2h2(cvt2h(sacc[nb][2], sacc[nb][3]));
            }
            // exact row sums of rounded P (fp32 accumulate)
            mma16816(lacc, aP, ONE2, ONE2);

            const uint32_t vrow = vln + (uint32_t)(kk * (16 * AROWB));
#pragma unroll
            for (int ng = 0; ng < 8; ng++) {
                uint32_t bv[4];
                LDSM4T(bv, vrow + ng * 32);
                mma16816(oacc[2 * ng],     aP, bv[0], bv[1]);
                mma16816(oacc[2 * ng + 1], aP, bv[2], bv[3]);
            }
        }

        __syncthreads();
        if (s + 2 < numkv)
            load_half_tile(vbase, vh, b, h, (s + 2) * 64, tid);
        asm volatile("cp.async.commit_group;" ::: "memory");
    }

    // ---- epilogue: O / l -> fp16 ----
    const float inv0 = 1.0f / lacc[0], inv1 = 1.0f / lacc[2];
    const int orow0 = i0 + wid * 16 + grp;
    const size_t ob0 = ((size_t)(b * T_ + orow0) * H_ + h) * D_ + tig * 2;
    const size_t ob1 = ((size_t)(b * T_ + orow0 + 8) * H_ + h) * D_ + tig * 2;
#pragma unroll
    for (int ng = 0; ng < 16; ng++) {
        *(uint32_t*)(oh + ob0 + ng * 8) =
            packh(oacc[ng][0] * inv0, oacc[ng][1] * inv0);
        *(uint32_t*)(oh + ob1 + ng * 8) =
            packh(oacc[ng][2] * inv1, oacc[ng][3] * inv1);
    }
}

// ---------------------------------------------------------------------------
// Launch (single stream, 4 kernels)
// ---------------------------------------------------------------------------
extern "C" void kernel_launch(void* const* d_in, const int* in_sizes, int n_in,
                              void* d_out, int out_size)
{
    const float* x    = (const float*)d_in[0];
    const float* w_aq = (const float*)d_in[1];
    const float* w_ak = (const float*)d_in[2];
    const float* w_av = (const float*)d_in[3];
    const float* w_ao = (const float*)d_in[4];
    float* out = (float*)d_out;

    __half *xh, *qh, *kh, *vh, *oh;
    cudaGetSymbolAddress((void**)&xh, g_xh);
    cudaGetSymbolAddress((void**)&qh, g_qh);
    cudaGetSymbolAddress((void**)&kh, g_kh);
    cudaGetSymbolAddress((void**)&vh, g_vh);
    cudaGetSymbolAddress((void**)&oh, g_oh);

    __half *wq, *wk, *wv, *wo;
    cudaGetSymbolAddress((void**)&wq, g_wq);
    cudaGetSymbolAddress((void**)&wk, g_wk);
    cudaGetSymbolAddress((void**)&wv, g_wv);
    cudaGetSymbolAddress((void**)&wo, g_wo);

    // One-launch fp32 -> fp16 conversion of x + all weights (no transposes)
    dim3 cg(4096, 6);
    conv_all<<<cg, 256>>>(x, w_aq, w_ak, w_av, w_ao, xh, wq, wk, wv, wo);

    // QKV projections with fused RoPE epilogue (4-warp fat-tile GEMM, BK=32,
    // 4-stage pipeline)
    cudaFuncSetAttribute(gemm_qkv,
                         cudaFuncAttributeMaxDynamicSharedMemorySize, GEMM_SMEM);
    cudaFuncSetAttribute(gemm_out,
                         cudaFuncAttributeMaxDynamicSharedMemorySize, GEMM_SMEM);
    dim3 gg(BT_ / 128, H_, 3);
    gemm_qkv<<<gg, GTHREADS, GEMM_SMEM>>>(xh, wq, wk, wv, qh, kh, vh);

    // HMMA flash attention -> oh (2 CTAs/SM)
    cudaFuncSetAttribute(attn_mma, cudaFuncAttributeMaxDynamicSharedMemorySize,
                         ATTN_SMEM);
    dim3 ga(T_ / 128, H_, B_);
    attn_mma<<<ga, 256, ATTN_SMEM>>>(qh, kh, vh, oh);

    // Output projection -> fp32 out
    dim3 ggo(BT_ / 128, M_ / 128, 1);
    gemm_out<<<ggo, GTHREADS, GEMM_SMEM>>>(oh, wo, out);
}